// round 7
// baseline (speedup 1.0000x reference)
#include <cuda_runtime.h>
#include <cstdint>

#define DIM        2048
#define NE         64
#define M_TOTAL    32768      // 4 * 8192
#define BM         128
#define BK         32
#define NTHREADS   256
#define NBLOCKS    (M_TOTAL / BM)   // 256
#define NTILES     (DIM / BK)       // 64
#define AS_STRIDE  134        // A tile row stride (floats): 2-way STS conflicts, 8B-aligned LDS
#define BS_STRIDE  66         // packed-B tile row stride (u64): 2-way STS, conflict-free LDS
#define SC_STRIDE  65         // scores row stride (floats)

// dynamic smem layout (bytes):
//   As0 @ 0        : 32*134*4 = 17152
//   As1 @ 17152    : 17152
//   Bs0 @ 34304    : 32*66*8 = 16896
//   Bs1 @ 51200    : 16896
//   total 68096;  scores (128*65*4 = 33280) unions over As0+As1
#define SMEM_BYTES 68096

// Deterministic per-block partial softmax-prob sums (no atomics).
__device__ float g_partial[NBLOCKS][NE];

// out layout (float32): [0,65536) indices, [65536,131072) weights, [131072] aux
#define OUT_W_OFF  (M_TOTAL * 2)
#define OUT_AUX    (M_TOTAL * 4)

typedef unsigned long long u64;

__device__ __forceinline__ u64 pack2(float v) {
    u64 r;
    asm("mov.b64 %0, {%1, %1};" : "=l"(r) : "f"(v));
    return r;
}

__device__ __forceinline__ void fma2(u64& acc, u64 a, u64 b) {
    asm("fma.rn.f32x2 %0, %1, %2, %0;" : "+l"(acc) : "l"(a), "l"(b));
}

__global__ __launch_bounds__(NTHREADS, 2)
void router_main(const float* __restrict__ x,
                 const float* __restrict__ W,
                 float* __restrict__ out) {
    extern __shared__ char dsm[];
    float* AsBuf[2];
    u64*   BsBuf[2];
    AsBuf[0] = reinterpret_cast<float*>(dsm);
    AsBuf[1] = reinterpret_cast<float*>(dsm + 17152);
    BsBuf[0] = reinterpret_cast<u64*>(dsm + 34304);
    BsBuf[1] = reinterpret_cast<u64*>(dsm + 51200);
    float* scores = reinterpret_cast<float*>(dsm);   // unions over As0/As1

    __shared__ float s_rowmax[BM];
    __shared__ float s_rowinv[BM];

    const int tid = threadIdx.x;
    const int tx  = tid & 15;             // expert lane: experts {tx, tx+16, tx+32, tx+48}
    const int ty  = tid >> 4;             // row group: 8 rows = 4 row-pairs

    // G2S index maps (fixed per thread)
    int aRow[4], aKq[4];
#pragma unroll
    for (int i = 0; i < 4; i++) {
        int idx = tid + i * NTHREADS;
        aRow[i] = idx >> 3;
        aKq[i]  = idx & 7;
    }
    int bEr[2], bKq[2];
#pragma unroll
    for (int i = 0; i < 2; i++) {
        int idx = tid + i * NTHREADS;
        bEr[i] = idx >> 3;
        bKq[i] = idx & 7;
    }

    const float* xblk = x + (size_t)blockIdx.x * BM * DIM;
    // per-thread gmem pointers, advanced by BK each tile
    const float4* aSrc[4];
#pragma unroll
    for (int i = 0; i < 4; i++)
        aSrc[i] = reinterpret_cast<const float4*>(xblk + (size_t)aRow[i] * DIM + aKq[i] * 4);
    const float4* bSrc[2];
#pragma unroll
    for (int i = 0; i < 2; i++)
        bSrc[i] = reinterpret_cast<const float4*>(W + (size_t)bEr[i] * DIM + bKq[i] * 4);

    // acc[pair i][j] : f32x2 over rows {ty*8+2i, ty*8+2i+1}, expert tx+16j
    u64 acc[4][4];
#pragma unroll
    for (int i = 0; i < 4; i++)
#pragma unroll
        for (int j = 0; j < 4; j++) acc[i][j] = 0ULL;

    float4 aReg[4], bReg[2];

    // ---- prologue: tile 0 ----
#pragma unroll
    for (int i = 0; i < 4; i++) aReg[i] = aSrc[i][0];
#pragma unroll
    for (int i = 0; i < 2; i++) bReg[i] = bSrc[i][0];
    {
        float* As = AsBuf[0];
        u64*   Bs = BsBuf[0];
#pragma unroll
        for (int i = 0; i < 4; i++) {
            int kb = aKq[i] * 4;
            As[(kb + 0) * AS_STRIDE + aRow[i]] = aReg[i].x;
            As[(kb + 1) * AS_STRIDE + aRow[i]] = aReg[i].y;
            As[(kb + 2) * AS_STRIDE + aRow[i]] = aReg[i].z;
            As[(kb + 3) * AS_STRIDE + aRow[i]] = aReg[i].w;
        }
#pragma unroll
        for (int i = 0; i < 2; i++) {
            int kb = bKq[i] * 4;
            Bs[(kb + 0) * BS_STRIDE + bEr[i]] = pack2(bReg[i].x);
            Bs[(kb + 1) * BS_STRIDE + bEr[i]] = pack2(bReg[i].y);
            Bs[(kb + 2) * BS_STRIDE + bEr[i]] = pack2(bReg[i].z);
            Bs[(kb + 3) * BS_STRIDE + bEr[i]] = pack2(bReg[i].w);
        }
    }
    __syncthreads();

    int p = 0;
#pragma unroll 1
    for (int t = 0; t < NTILES; t++) {
        const bool more = t + 1 < NTILES;
        // ---- prefetch next tile into registers ----
        if (more) {
            int off = (t + 1) * (BK / 4);
#pragma unroll
            for (int i = 0; i < 4; i++) aReg[i] = aSrc[i][off];
#pragma unroll
            for (int i = 0; i < 2; i++) bReg[i] = bSrc[i][off];
        }

        // ---- compute current tile ----
        {
            const float* As = AsBuf[p];
            const u64*   Bs = BsBuf[p];
#pragma unroll
            for (int kk = 0; kk < BK; kk++) {
                const u64* ar = reinterpret_cast<const u64*>(As + kk * AS_STRIDE + ty * 8);
                u64 a0 = ar[0], a1 = ar[1], a2 = ar[2], a3 = ar[3];
                const u64* br = Bs + kk * BS_STRIDE + tx;
                u64 b0 = br[0], b1 = br[16], b2 = br[32], b3 = br[48];
                fma2(acc[0][0], a0, b0); fma2(acc[0][1], a0, b1);
                fma2(acc[0][2], a0, b2); fma2(acc[0][3], a0, b3);
                fma2(acc[1][0], a1, b0); fma2(acc[1][1], a1, b1);
                fma2(acc[1][2], a1, b2); fma2(acc[1][3], a1, b3);
                fma2(acc[2][0], a2, b0); fma2(acc[2][1], a2, b1);
                fma2(acc[2][2], a2, b2); fma2(acc[2][3], a2, b3);
                fma2(acc[3][0], a3, b0); fma2(acc[3][1], a3, b1);
                fma2(acc[3][2], a3, b2); fma2(acc[3][3], a3, b3);
            }
        }

        // ---- store prefetched tile into the other buffer (safe: not being read) ----
        if (more) {
            float* As = AsBuf[p ^ 1];
            u64*   Bs = BsBuf[p ^ 1];
#pragma unroll
            for (int i = 0; i < 4; i++) {
                int kb = aKq[i] * 4;
                As[(kb + 0) * AS_STRIDE + aRow[i]] = aReg[i].x;
                As[(kb + 1) * AS_STRIDE + aRow[i]] = aReg[i].y;
                As[(kb + 2) * AS_STRIDE + aRow[i]] = aReg[i].z;
                As[(kb + 3) * AS_STRIDE + aRow[i]] = aReg[i].w;
            }
#pragma unroll
            for (int i = 0; i < 2; i++) {
                int kb = bKq[i] * 4;
                Bs[(kb + 0) * BS_STRIDE + bEr[i]] = pack2(bReg[i].x);
                Bs[(kb + 1) * BS_STRIDE + bEr[i]] = pack2(bReg[i].y);
                Bs[(kb + 2) * BS_STRIDE + bEr[i]] = pack2(bReg[i].z);
                Bs[(kb + 3) * BS_STRIDE + bEr[i]] = pack2(bReg[i].w);
            }
        }
        __syncthreads();
        p ^= 1;
    }

    // ---- scatter scores into smem [128][65] (unions over A buffers) ----
#pragma unroll
    for (int i = 0; i < 4; i++) {
        int row0 = ty * 8 + 2 * i;
#pragma unroll
        for (int j = 0; j < 4; j++) {
            int e = tx + 16 * j;
            u64 pck = acc[i][j];
            float lo = __uint_as_float((unsigned)(pck & 0xffffffffULL));
            float hi = __uint_as_float((unsigned)(pck >> 32));
            scores[row0 * SC_STRIDE + e]       = lo;
            scores[(row0 + 1) * SC_STRIDE + e] = hi;
        }
    }
    __syncthreads();

    // ---- phase 1: per-row top-2, weights, row softmax stats ----
    if (tid < BM) {
        const float* srow = scores + tid * SC_STRIDE;
        float v0 = -3.4e38f, v1 = -3.4e38f;
        int i0 = 0, i1 = 0;
#pragma unroll
        for (int e = 0; e < NE; e++) {
            float s = srow[e];
            if (s > v0) { v1 = v0; i1 = i0; v0 = s; i0 = e; }
            else if (s > v1) { v1 = s; i1 = e; }
        }
        float sum = 0.0f;
#pragma unroll
        for (int e = 0; e < NE; e++) sum += __expf(srow[e] - v0);
        s_rowmax[tid] = v0;
        s_rowinv[tid] = 1.0f / sum;

        float t  = __expf(v1 - v0);
        float w0 = 1.0f / (1.0f + t);
        float w1 = t * w0;

        size_t g = (size_t)blockIdx.x * BM + tid;
        out[2 * g]     = (float)i0;
        out[2 * g + 1] = (float)i1;
        out[OUT_W_OFF + 2 * g]     = w0;
        out[OUT_W_OFF + 2 * g + 1] = w1;
    }
    __syncthreads();

    // ---- phase 2: per-expert partial sum of softmax probs over this block's rows ----
    if (tid < NE) {
        float a = 0.0f;
#pragma unroll 8
        for (int r = 0; r < BM; r++) {
            a += __expf(scores[r * SC_STRIDE + tid] - s_rowmax[r]) * s_rowinv[r];
        }
        g_partial[blockIdx.x][tid] = a;
    }
}

__global__ void router_finalize(float* __restrict__ out) {
    __shared__ float part[8][NE];
    __shared__ float red[NE];
    const int tid = threadIdx.x;      // 512 threads
    const int c = tid >> 6;           // chunk 0..7 (32 blocks each)
    const int e = tid & 63;
    float s = 0.0f;
#pragma unroll 4
    for (int b = c * 32; b < c * 32 + 32; b++) s += g_partial[b][e];
    part[c][e] = s;
    __syncthreads();
    if (tid < NE) {
        float t = 0.0f;
#pragma unroll
        for (int i = 0; i < 8; i++) t += part[i][tid];
        t *= (1.0f / (float)M_TOTAL);
        red[tid] = t * t;
    }
    __syncthreads();
    if (tid == 0) {
        float t = 0.0f;
#pragma unroll
        for (int i = 0; i < NE; i++) t += red[i];
        out[OUT_AUX] = (float)NE * t;
    }
}

extern "C" void kernel_launch(void* const* d_in, const int* in_sizes, int n_in,
                              void* d_out, int out_size) {
    const float* x = (const float*)d_in[0];   // [4, 8192, 2048] f32
    const float* W = (const float*)d_in[1];   // [64, 2048] f32
    float* out = (float*)d_out;

    static int attr_done = 0;
    if (!attr_done) {
        cudaFuncSetAttribute(router_main,
                             cudaFuncAttributeMaxDynamicSharedMemorySize, SMEM_BYTES);
        attr_done = 1;
    }

    router_main<<<NBLOCKS, NTHREADS, SMEM_BYTES>>>(x, W, out);
    router_finalize<<<1, 512>>>(out);
}

// round 8
// speedup vs baseline: 1.6098x; 1.6098x over previous
#include <cuda_runtime.h>
#include <cstdint>

#define DIM        2048
#define NE         64
#define M_TOTAL    32768      // 4 * 8192
#define BM         128
#define BK         32
#define NTHREADS   256
#define NBLOCKS    (M_TOTAL / BM)   // 256
#define NTILES     (DIM / BK)       // 64
#define AS_STRIDE  134        // A tile row stride (floats): 2-way STS banks, 8B-aligned LDS
#define BS_STRIDE  68         // B tile row stride (floats): 4-way STS banks, 16B-aligned LDS.128
#define SC_STRIDE  65         // scores row stride (floats) -> conflict-free

// Deterministic per-block partial softmax-prob sums (no atomics on data).
__device__ float g_partial[NBLOCKS][NE];
__device__ unsigned int g_count = 0;   // ticket counter; last block resets -> replay-safe

// out layout (float32): [0,65536) indices, [65536,131072) weights, [131072] aux
#define OUT_W_OFF  (M_TOTAL * 2)
#define OUT_AUX    (M_TOTAL * 4)

typedef unsigned long long u64;

__device__ __forceinline__ u64 pack2(float v) {
    u64 r;
    asm("mov.b64 %0, {%1, %1};" : "=l"(r) : "f"(v));
    return r;
}

__device__ __forceinline__ void fma2(u64& acc, u64 a, u64 b) {
    asm("fma.rn.f32x2 %0, %1, %2, %0;" : "+l"(acc) : "l"(a), "l"(b));
}

__global__ __launch_bounds__(NTHREADS)
void router_main(const float* __restrict__ x,
                 const float* __restrict__ W,
                 float* __restrict__ out) {
    // smem union: GEMM tiles (As 32x134 + Bs 32x68 = 25.9KB) then scores (128x65 = 33.3KB)
    __shared__ float sm[BM * SC_STRIDE];   // 8320 floats
    __shared__ float s_rowmax[BM];
    __shared__ float s_rowinv[BM];
    __shared__ float s_part[4][NE];
    __shared__ unsigned int s_rank;

    float* As = sm;                       // [BK][AS_STRIDE]  k-major, m contiguous
    float* Bs = sm + BK * AS_STRIDE;      // [BK][BS_STRIDE]  k-major, e contiguous

    const int tid = threadIdx.x;
    const int tx  = tid & 15;             // expert group: 4 experts (tx*4 .. tx*4+3)
    const int ty  = tid >> 4;             // row group: 8 rows = 4 row-pairs

    // G2S index maps (fixed per thread)
    int aRow[4], aKq[4];
#pragma unroll
    for (int i = 0; i < 4; i++) {
        int idx = tid + i * NTHREADS;
        aRow[i] = idx >> 3;
        aKq[i]  = idx & 7;
    }
    int bEr[2], bKq[2];
#pragma unroll
    for (int i = 0; i < 2; i++) {
        int idx = tid + i * NTHREADS;
        bEr[i] = idx >> 3;
        bKq[i] = idx & 7;
    }

    const float* xblk = x + (size_t)blockIdx.x * BM * DIM;

    // acc[pair i][expert j] : packed f32x2 over rows {ty*8+2i, ty*8+2i+1}
    u64 acc[4][4];
#pragma unroll
    for (int i = 0; i < 4; i++)
#pragma unroll
        for (int j = 0; j < 4; j++) acc[i][j] = 0ULL;

    float4 aReg[4], bReg[2];

    // ---- prologue: load tile 0 into registers, store to smem ----
#pragma unroll
    for (int i = 0; i < 4; i++)
        aReg[i] = *reinterpret_cast<const float4*>(xblk + (size_t)aRow[i] * DIM + aKq[i] * 4);
#pragma unroll
    for (int i = 0; i < 2; i++)
        bReg[i] = *reinterpret_cast<const float4*>(W + (size_t)bEr[i] * DIM + bKq[i] * 4);

#pragma unroll
    for (int i = 0; i < 4; i++) {
        int kb = aKq[i] * 4;
        As[(kb + 0) * AS_STRIDE + aRow[i]] = aReg[i].x;
        As[(kb + 1) * AS_STRIDE + aRow[i]] = aReg[i].y;
        As[(kb + 2) * AS_STRIDE + aRow[i]] = aReg[i].z;
        As[(kb + 3) * AS_STRIDE + aRow[i]] = aReg[i].w;
    }
#pragma unroll
    for (int i = 0; i < 2; i++) {
        int kb = bKq[i] * 4;
        Bs[(kb + 0) * BS_STRIDE + bEr[i]] = bReg[i].x;
        Bs[(kb + 1) * BS_STRIDE + bEr[i]] = bReg[i].y;
        Bs[(kb + 2) * BS_STRIDE + bEr[i]] = bReg[i].z;
        Bs[(kb + 3) * BS_STRIDE + bEr[i]] = bReg[i].w;
    }
    __syncthreads();

#pragma unroll 1
    for (int t = 0; t < NTILES; t++) {
        const bool more = t + 1 < NTILES;
        // ---- prefetch next tile into registers (LDGs overlap compute) ----
        if (more) {
            int kn = (t + 1) * BK;
#pragma unroll
            for (int i = 0; i < 4; i++)
                aReg[i] = *reinterpret_cast<const float4*>(xblk + (size_t)aRow[i] * DIM + kn + aKq[i] * 4);
#pragma unroll
            for (int i = 0; i < 2; i++)
                bReg[i] = *reinterpret_cast<const float4*>(W + (size_t)bEr[i] * DIM + kn + bKq[i] * 4);
        }

        // ---- compute current tile ----
#pragma unroll
        for (int kk = 0; kk < BK; kk++) {
            const u64* ar = reinterpret_cast<const u64*>(As + kk * AS_STRIDE + ty * 8);
            u64 a0 = ar[0], a1 = ar[1], a2 = ar[2], a3 = ar[3];
            float4 bv = *reinterpret_cast<const float4*>(Bs + kk * BS_STRIDE + tx * 4);
            u64 b0 = pack2(bv.x);
            u64 b1 = pack2(bv.y);
            u64 b2 = pack2(bv.z);
            u64 b3 = pack2(bv.w);
            fma2(acc[0][0], a0, b0); fma2(acc[0][1], a0, b1);
            fma2(acc[0][2], a0, b2); fma2(acc[0][3], a0, b3);
            fma2(acc[1][0], a1, b0); fma2(acc[1][1], a1, b1);
            fma2(acc[1][2], a1, b2); fma2(acc[1][3], a1, b3);
            fma2(acc[2][0], a2, b0); fma2(acc[2][1], a2, b1);
            fma2(acc[2][2], a2, b2); fma2(acc[2][3], a2, b3);
            fma2(acc[3][0], a3, b0); fma2(acc[3][1], a3, b1);
            fma2(acc[3][2], a3, b2); fma2(acc[3][3], a3, b3);
        }
        __syncthreads();   // everyone done READING this tile

        // ---- store prefetched tile ----
        if (more) {
#pragma unroll
            for (int i = 0; i < 4; i++) {
                int kb = aKq[i] * 4;
                As[(kb + 0) * AS_STRIDE + aRow[i]] = aReg[i].x;
                As[(kb + 1) * AS_STRIDE + aRow[i]] = aReg[i].y;
                As[(kb + 2) * AS_STRIDE + aRow[i]] = aReg[i].z;
                As[(kb + 3) * AS_STRIDE + aRow[i]] = aReg[i].w;
            }
#pragma unroll
            for (int i = 0; i < 2; i++) {
                int kb = bKq[i] * 4;
                Bs[(kb + 0) * BS_STRIDE + bEr[i]] = bReg[i].x;
                Bs[(kb + 1) * BS_STRIDE + bEr[i]] = bReg[i].y;
                Bs[(kb + 2) * BS_STRIDE + bEr[i]] = bReg[i].z;
                Bs[(kb + 3) * BS_STRIDE + bEr[i]] = bReg[i].w;
            }
            __syncthreads();   // tile visible before next compute
        }
    }

    // ---- scatter scores into smem [128][65] ----
#pragma unroll
    for (int i = 0; i < 4; i++) {
        int row0 = ty * 8 + 2 * i;
#pragma unroll
        for (int j = 0; j < 4; j++) {
            int e = tx * 4 + j;
            u64 p = acc[i][j];
            float lo = __uint_as_float((unsigned)(p & 0xffffffffULL));
            float hi = __uint_as_float((unsigned)(p >> 32));
            sm[row0 * SC_STRIDE + e]       = lo;
            sm[(row0 + 1) * SC_STRIDE + e] = hi;
        }
    }
    __syncthreads();

    // ---- phase 1: per-row top-2, weights, row softmax stats ----
    if (tid < BM) {
        const float* srow = sm + tid * SC_STRIDE;
        float v0 = -3.4e38f, v1 = -3.4e38f;
        int i0 = 0, i1 = 0;
#pragma unroll
        for (int e = 0; e < NE; e++) {
            float s = srow[e];
            if (s > v0) { v1 = v0; i1 = i0; v0 = s; i0 = e; }
            else if (s > v1) { v1 = s; i1 = e; }
        }
        float sum = 0.0f;
#pragma unroll
        for (int e = 0; e < NE; e++) sum += __expf(srow[e] - v0);
        s_rowmax[tid] = v0;
        s_rowinv[tid] = 1.0f / sum;

        float t  = __expf(v1 - v0);
        float w0 = 1.0f / (1.0f + t);
        float w1 = t * w0;

        size_t g = (size_t)blockIdx.x * BM + tid;
        out[2 * g]     = (float)i0;
        out[2 * g + 1] = (float)i1;
        out[OUT_W_OFF + 2 * g]     = w0;
        out[OUT_W_OFF + 2 * g + 1] = w1;
    }
    __syncthreads();

    // ---- phase 2: per-expert partial sum of softmax probs over this block's rows ----
    if (tid < NE) {
        float a = 0.0f;
#pragma unroll 8
        for (int r = 0; r < BM; r++) {
            a += __expf(sm[r * SC_STRIDE + tid] - s_rowmax[r]) * s_rowinv[r];
        }
        g_partial[blockIdx.x][tid] = a;
    }
    __syncthreads();

    // ---- fused finalize: last block to arrive reduces all partials ----
    if (tid == 0) {
        __threadfence();                       // publish g_partial before ticket
        s_rank = atomicAdd(&g_count, 1u);
    }
    __syncthreads();
    if (s_rank == NBLOCKS - 1) {
        __threadfence();                       // acquire all blocks' g_partial
        const int c = tid >> 6;                // chunk 0..3 (64 blocks each)
        const int e = tid & 63;
        float s = 0.0f;
#pragma unroll 4
        for (int b = c * 64; b < c * 64 + 64; b++) s += g_partial[b][e];
        s_part[c][e] = s;
        __syncthreads();
        if (tid < NE) {
            float t = s_part[0][tid] + s_part[1][tid] + s_part[2][tid] + s_part[3][tid];
            t *= (1.0f / (float)M_TOTAL);
            s_part[0][tid] = t * t;
        }
        __syncthreads();
        if (tid == 0) {
            float t = 0.0f;
#pragma unroll
            for (int i = 0; i < NE; i++) t += s_part[0][i];
            out[OUT_AUX] = (float)NE * t;
            g_count = 0;                       // reset for next graph replay
        }
    }
}

extern "C" void kernel_launch(void* const* d_in, const int* in_sizes, int n_in,
                              void* d_out, int out_size) {
    const float* x = (const float*)d_in[0];   // [4, 8192, 2048] f32
    const float* W = (const float*)d_in[1];   // [64, 2048] f32
    float* out = (float*)d_out;

    router_main<<<NBLOCKS, NTHREADS>>>(x, W, out);
}